// round 4
// baseline (speedup 1.0000x reference)
#include <cuda_runtime.h>
#include <math.h>

// Problem constants
#define BB   2
#define SS   2048
#define EE   1024
#define NHH  16
#define NKVV 4
#define HDD  64
#define GCH  12
#define MM   (BB * SS)        // 4096 tokens
#define QDIM (NHH * HDD)      // 1024
#define KVDIM (NKVV * HDD)    // 256

// Scratch (device globals: allocation-free rule)
__device__ float g_q[MM * QDIM];    // 16 MB
__device__ float g_k[MM * KVDIM];   //  4 MB
__device__ float g_v[MM * KVDIM];   //  4 MB
__device__ float g_y[MM * QDIM];    // 16 MB

// ---------------------------------------------------------------------------
// GEMM 1: [q|k|v] = X (4096x1024) @ [Wq;Wk;Wv]^T (1536x1024), NT, fp32
// 128x128x8 tile, 256 threads, 8x8 micro-tile
// ---------------------------------------------------------------------------
__global__ void __launch_bounds__(256) gemm_qkv(
    const float* __restrict__ X,
    const float* __restrict__ Wq,
    const float* __restrict__ Wk,
    const float* __restrict__ Wv)
{
    __shared__ float As[8][128];
    __shared__ float Bs[8][128];
    const int bm = blockIdx.y * 128;
    const int bn = blockIdx.x * 128;
    const int tid = threadIdx.x;
    const int lrow = tid >> 1;
    const int lcol = (tid & 1) * 4;
    const int ty = tid >> 4;
    const int tx = tid & 15;

    const float* arow = X + (size_t)(bm + lrow) * EE + lcol;
    const int n = bn + lrow;
    const float* wrow;
    if (n < QDIM)                wrow = Wq + (size_t)n * EE + lcol;
    else if (n < QDIM + KVDIM)   wrow = Wk + (size_t)(n - QDIM) * EE + lcol;
    else                         wrow = Wv + (size_t)(n - QDIM - KVDIM) * EE + lcol;

    float acc[8][8];
    #pragma unroll
    for (int i = 0; i < 8; i++)
        #pragma unroll
        for (int j = 0; j < 8; j++) acc[i][j] = 0.f;

    for (int k0 = 0; k0 < EE; k0 += 8) {
        float4 av = *(const float4*)(arow + k0);
        float4 bv = *(const float4*)(wrow + k0);
        __syncthreads();
        As[lcol + 0][lrow] = av.x; As[lcol + 1][lrow] = av.y;
        As[lcol + 2][lrow] = av.z; As[lcol + 3][lrow] = av.w;
        Bs[lcol + 0][lrow] = bv.x; Bs[lcol + 1][lrow] = bv.y;
        Bs[lcol + 2][lrow] = bv.z; Bs[lcol + 3][lrow] = bv.w;
        __syncthreads();
        #pragma unroll
        for (int k = 0; k < 8; k++) {
            float4 a0 = *(const float4*)&As[k][ty * 8];
            float4 a1 = *(const float4*)&As[k][ty * 8 + 4];
            float4 b0 = *(const float4*)&Bs[k][tx * 8];
            float4 b1 = *(const float4*)&Bs[k][tx * 8 + 4];
            float af[8] = {a0.x, a0.y, a0.z, a0.w, a1.x, a1.y, a1.z, a1.w};
            float bf[8] = {b0.x, b0.y, b0.z, b0.w, b1.x, b1.y, b1.z, b1.w};
            #pragma unroll
            for (int i = 0; i < 8; i++)
                #pragma unroll
                for (int j = 0; j < 8; j++)
                    acc[i][j] = fmaf(af[i], bf[j], acc[i][j]);
        }
    }

    #pragma unroll
    for (int i = 0; i < 8; i++) {
        const int row = bm + ty * 8 + i;
        #pragma unroll
        for (int j = 0; j < 8; j++) {
            const int nn = bn + tx * 8 + j;
            const float v = acc[i][j];
            if (nn < QDIM)               g_q[(size_t)row * QDIM + nn] = v;
            else if (nn < QDIM + KVDIM)  g_k[(size_t)row * KVDIM + (nn - QDIM)] = v;
            else                         g_v[(size_t)row * KVDIM + (nn - QDIM - KVDIM)] = v;
        }
    }
}

// ---------------------------------------------------------------------------
// GEMM 2: out = y (4096x1024) @ Wproj^T (1024x1024)
// ---------------------------------------------------------------------------
__global__ void __launch_bounds__(256) gemm_proj(
    const float* __restrict__ W, float* __restrict__ C)
{
    __shared__ float As[8][128];
    __shared__ float Bs[8][128];
    const int bm = blockIdx.y * 128;
    const int bn = blockIdx.x * 128;
    const int tid = threadIdx.x;
    const int lrow = tid >> 1;
    const int lcol = (tid & 1) * 4;
    const int ty = tid >> 4;
    const int tx = tid & 15;

    const float* arow = g_y + (size_t)(bm + lrow) * EE + lcol;
    const float* wrow = W + (size_t)(bn + lrow) * EE + lcol;

    float acc[8][8];
    #pragma unroll
    for (int i = 0; i < 8; i++)
        #pragma unroll
        for (int j = 0; j < 8; j++) acc[i][j] = 0.f;

    for (int k0 = 0; k0 < EE; k0 += 8) {
        float4 av = *(const float4*)(arow + k0);
        float4 bv = *(const float4*)(wrow + k0);
        __syncthreads();
        As[lcol + 0][lrow] = av.x; As[lcol + 1][lrow] = av.y;
        As[lcol + 2][lrow] = av.z; As[lcol + 3][lrow] = av.w;
        Bs[lcol + 0][lrow] = bv.x; Bs[lcol + 1][lrow] = bv.y;
        Bs[lcol + 2][lrow] = bv.z; Bs[lcol + 3][lrow] = bv.w;
        __syncthreads();
        #pragma unroll
        for (int k = 0; k < 8; k++) {
            float4 a0 = *(const float4*)&As[k][ty * 8];
            float4 a1 = *(const float4*)&As[k][ty * 8 + 4];
            float4 b0 = *(const float4*)&Bs[k][tx * 8];
            float4 b1 = *(const float4*)&Bs[k][tx * 8 + 4];
            float af[8] = {a0.x, a0.y, a0.z, a0.w, a1.x, a1.y, a1.z, a1.w};
            float bf[8] = {b0.x, b0.y, b0.z, b0.w, b1.x, b1.y, b1.z, b1.w};
            #pragma unroll
            for (int i = 0; i < 8; i++)
                #pragma unroll
                for (int j = 0; j < 8; j++)
                    acc[i][j] = fmaf(af[i], bf[j], acc[i][j]);
        }
    }

    #pragma unroll
    for (int i = 0; i < 8; i++) {
        const int row = bm + ty * 8 + i;
        #pragma unroll
        for (int j = 0; j < 8; j++)
            C[(size_t)row * EE + bn + tx * 8 + j] = acc[i][j];
    }
}

// ---------------------------------------------------------------------------
// Epilogue: RoPE + RMS-norm on q (16 heads) and k (4 heads); gated ve add
// on v (4 heads). One warp per (token, unit), unit in [0,24).
// ---------------------------------------------------------------------------
__global__ void __launch_bounds__(128) rope_gate(
    const float* __restrict__ X, const float* __restrict__ VE,
    const float* __restrict__ Cos, const float* __restrict__ Sin,
    const float* __restrict__ Wgate)
{
    const int gw = blockIdx.x * 4 + (threadIdx.x >> 5);
    const int lane = threadIdx.x & 31;
    const int token = gw / 24;
    const int unit = gw - token * 24;
    const int s = token & (SS - 1);

    if (unit >= 20) {  // v gate
        const int kv = unit - 20;
        const float* xr = X + (size_t)token * EE;
        float g = 0.f;
        #pragma unroll
        for (int c = 0; c < GCH; c++) g = fmaf(xr[c], Wgate[kv * GCH + c], g);
        g = 3.f / (1.f + __expf(-g));
        float* vb = g_v + (size_t)token * KVDIM + kv * HDD;
        const float* veb = VE + (size_t)token * KVDIM + kv * HDD;
        vb[lane]      += g * veb[lane];
        vb[lane + 32] += g * veb[lane + 32];
        return;
    }

    float* base = (unit < NHH)
        ? g_q + (size_t)token * QDIM + unit * HDD
        : g_k + (size_t)token * KVDIM + (unit - NHH) * HDD;

    const float c  = Cos[s * 32 + lane];
    const float sn = Sin[s * 32 + lane];
    const float x1 = base[lane];
    const float x2 = base[lane + 32];
    const float o1 =  x1 * c + x2 * sn;
    const float o2 = -x1 * sn + x2 * c;
    float ssum = o1 * o1 + o2 * o2;
    #pragma unroll
    for (int off = 16; off; off >>= 1)
        ssum += __shfl_xor_sync(0xffffffffu, ssum, off);
    const float inv = rsqrtf(ssum * (1.f / 64.f) + 1.1920928955078125e-07f) * 1.2f;
    base[lane]      = o1 * inv;
    base[lane + 32] = o2 * inv;
}

// ---------------------------------------------------------------------------
// Flash attention: causal, GQA (4 q-heads per kv head), 64x64 tiles.
// 256 threads, 4x4 fragments, online softmax, K/V share one smem buffer.
// smem: Qs 64x65 | KVs 64x65 | Ps 64x65  = 49920 B (dynamic)
// ---------------------------------------------------------------------------
#define ATTN_SMEM_BYTES (3 * 64 * 65 * 4)

__global__ void __launch_bounds__(256) attn_kernel()
{
    extern __shared__ float sm[];
    float* Qs  = sm;
    float* KVs = sm + 64 * 65;
    float* Ps  = sm + 2 * 64 * 65;

    const int qt = blockIdx.x;            // q tile (32)
    const int h  = blockIdx.y;            // head (16)
    const int b  = blockIdx.z;            // batch (2)
    const int hkv = h >> 2;
    const int q0 = qt * 64;
    const int tid = threadIdx.x;
    const int ty = tid >> 4, tx = tid & 15;

    for (int idx = tid; idx < 64 * 64; idx += 256) {
        const int r = idx >> 6, d = idx & 63;
        Qs[r * 65 + d] = g_q[(size_t)(b * SS + q0 + r) * QDIM + h * HDD + d];
    }

    float Oa[4][4];
    float mrow[4], lrow[4];
    #pragma unroll
    for (int i = 0; i < 4; i++) {
        mrow[i] = -1e30f; lrow[i] = 0.f;
        #pragma unroll
        for (int j = 0; j < 4; j++) Oa[i][j] = 0.f;
    }

    for (int j = 0; j <= qt; j++) {
        __syncthreads();  // prior-iter KVs/Ps consumers finished; Qs visible on iter 0
        const int kbase = b * SS + j * 64;
        for (int idx = tid; idx < 64 * 64; idx += 256) {
            const int r = idx >> 6, d = idx & 63;
            KVs[r * 65 + d] = g_k[(size_t)(kbase + r) * KVDIM + hkv * HDD + d];
        }
        __syncthreads();

        // S = Q K^T
        float sf[4][4];
        #pragma unroll
        for (int i = 0; i < 4; i++)
            #pragma unroll
            for (int jj = 0; jj < 4; jj++) sf[i][jj] = 0.f;
        #pragma unroll 16
        for (int d = 0; d < 64; d++) {
            float qf[4], kf[4];
            #pragma unroll
            for (int i = 0; i < 4; i++)  qf[i]  = Qs[(ty * 4 + i) * 65 + d];
            #pragma unroll
            for (int jj = 0; jj < 4; jj++) kf[jj] = KVs[(tx * 4 + jj) * 65 + d];
            #pragma unroll
            for (int i = 0; i < 4; i++)
                #pragma unroll
                for (int jj = 0; jj < 4; jj++)
                    sf[i][jj] = fmaf(qf[i], kf[jj], sf[i][jj]);
        }

        // scale + causal mask (diagonal tile only)
        if (j == qt) {
            #pragma unroll
            for (int i = 0; i < 4; i++)
                #pragma unroll
                for (int jj = 0; jj < 4; jj++) {
                    const int r = ty * 4 + i, c = tx * 4 + jj;
                    sf[i][jj] = (c <= r) ? sf[i][jj] * 0.125f : -1e30f;
                }
        } else {
            #pragma unroll
            for (int i = 0; i < 4; i++)
                #pragma unroll
                for (int jj = 0; jj < 4; jj++) sf[i][jj] *= 0.125f;
        }

        // online softmax row stats (reduce across 16-lane tx groups)
        float scl[4];
        #pragma unroll
        for (int i = 0; i < 4; i++) {
            float mx = fmaxf(fmaxf(sf[i][0], sf[i][1]), fmaxf(sf[i][2], sf[i][3]));
            #pragma unroll
            for (int off = 8; off; off >>= 1)
                mx = fmaxf(mx, __shfl_xor_sync(0xffffffffu, mx, off));
            const float mnew = fmaxf(mrow[i], mx);
            float ps = 0.f;
            #pragma unroll
            for (int jj = 0; jj < 4; jj++) {
                sf[i][jj] = __expf(sf[i][jj] - mnew);
                ps += sf[i][jj];
            }
            #pragma unroll
            for (int off = 8; off; off >>= 1)
                ps += __shfl_xor_sync(0xffffffffu, ps, off);
            scl[i] = __expf(mrow[i] - mnew);
            lrow[i] = lrow[i] * scl[i] + ps;
            mrow[i] = mnew;
        }

        __syncthreads();  // everyone done reading K

        // stage P, load V over K's buffer, rescale O
        #pragma unroll
        for (int i = 0; i < 4; i++)
            #pragma unroll
            for (int jj = 0; jj < 4; jj++)
                Ps[(ty * 4 + i) * 65 + tx * 4 + jj] = sf[i][jj];
        for (int idx = tid; idx < 64 * 64; idx += 256) {
            const int r = idx >> 6, d = idx & 63;
            KVs[r * 65 + d] = g_v[(size_t)(kbase + r) * KVDIM + hkv * HDD + d];
        }
        #pragma unroll
        for (int i = 0; i < 4; i++)
            #pragma unroll
            for (int jj = 0; jj < 4; jj++) Oa[i][jj] *= scl[i];
        __syncthreads();

        // O += P V
        #pragma unroll 16
        for (int kk = 0; kk < 64; kk++) {
            float pf[4], vf[4];
            #pragma unroll
            for (int i = 0; i < 4; i++)  pf[i]  = Ps[(ty * 4 + i) * 65 + kk];
            #pragma unroll
            for (int jj = 0; jj < 4; jj++) vf[jj] = KVs[kk * 65 + tx * 4 + jj];
            #pragma unroll
            for (int i = 0; i < 4; i++)
                #pragma unroll
                for (int jj = 0; jj < 4; jj++)
                    Oa[i][jj] = fmaf(pf[i], vf[jj], Oa[i][jj]);
        }
    }

    #pragma unroll
    for (int i = 0; i < 4; i++) {
        const float invl = 1.f / lrow[i];
        const int r = q0 + ty * 4 + i;
        #pragma unroll
        for (int jj = 0; jj < 4; jj++)
            g_y[(size_t)(b * SS + r) * QDIM + h * HDD + tx * 4 + jj] = Oa[i][jj] * invl;
    }
}

// ---------------------------------------------------------------------------
// Launch: qkv GEMM -> rope/rms/gate -> flash attention -> proj GEMM
// Inputs: 0 x, 1 ve, 2 cos, 3 sin, 4 attn_mask(unused), 5 Wq, 6 Wk, 7 Wv,
//         8 Wproj, 9 Wgate. Output: float32 (B,S,E).
// ---------------------------------------------------------------------------
extern "C" void kernel_launch(void* const* d_in, const int* in_sizes, int n_in,
                              void* d_out, int out_size)
{
    const float* x     = (const float*)d_in[0];
    const float* ve    = (const float*)d_in[1];
    const float* cosb  = (const float*)d_in[2];
    const float* sinb  = (const float*)d_in[3];
    const float* Wq    = (const float*)d_in[5];
    const float* Wk    = (const float*)d_in[6];
    const float* Wv    = (const float*)d_in[7];
    const float* Wproj = (const float*)d_in[8];
    const float* Wgate = (const float*)d_in[9];
    float* out = (float*)d_out;

    (void)in_sizes; (void)n_in; (void)out_size;

    cudaFuncSetAttribute(attn_kernel,
                         cudaFuncAttributeMaxDynamicSharedMemorySize,
                         ATTN_SMEM_BYTES);

    // 1) QKV projection: grid (1536/128, 4096/128)
    gemm_qkv<<<dim3(12, 32), 256>>>(x, Wq, Wk, Wv);

    // 2) RoPE + RMS + gated-ve: 4096 tokens * 24 warp-units / 4 warps per block
    rope_gate<<<(MM * 24) / 4, 128>>>(x, ve, cosb, sinb, Wgate);

    // 3) Flash attention: (q-tiles, heads, batch)
    attn_kernel<<<dim3(SS / 64, NHH, BB), 256, ATTN_SMEM_BYTES>>>();

    // 4) Output projection: grid (1024/128, 4096/128)
    gemm_proj<<<dim3(8, 32), 256>>>(Wproj, out);
}

// round 5
// speedup vs baseline: 3.2264x; 3.2264x over previous
#include <cuda_runtime.h>
#include <math.h>
#include <stdint.h>

// Problem constants
#define BB   2
#define SS   2048
#define EE   1024
#define NHH  16
#define NKVV 4
#define HDD  64
#define GCH  12
#define MM   (BB * SS)        // 4096 tokens
#define QDIM (NHH * HDD)      // 1024
#define KVDIM (NKVV * HDD)    // 256

// Scratch (device globals: allocation-free rule)
__device__ float g_q[MM * QDIM];    // 16 MB
__device__ float g_k[MM * KVDIM];   //  4 MB
__device__ float g_v[MM * KVDIM];   //  4 MB
__device__ float g_y[MM * QDIM];    // 16 MB

// ---------------------------------------------------------------------------
// tf32 helpers
// ---------------------------------------------------------------------------
__device__ __forceinline__ unsigned f2tf(float x) {
    unsigned u;
    asm("cvt.rna.tf32.f32 %0, %1;" : "=r"(u) : "f"(x));
    return u;
}

// D += A(16x8) * B(8x8), tf32 inputs, f32 accumulate
__device__ __forceinline__ void mma8(float* c,
                                     unsigned a0, unsigned a1, unsigned a2, unsigned a3,
                                     unsigned b0, unsigned b1) {
    asm volatile(
        "mma.sync.aligned.m16n8k8.row.col.f32.tf32.tf32.f32 "
        "{%0,%1,%2,%3},{%4,%5,%6,%7},{%8,%9},{%0,%1,%2,%3};"
        : "+f"(c[0]), "+f"(c[1]), "+f"(c[2]), "+f"(c[3])
        : "r"(a0), "r"(a1), "r"(a2), "r"(a3), "r"(b0), "r"(b1));
}

__device__ __forceinline__ float* qkv_ptr(int row, int col) {
    if (col < QDIM)         return &g_q[(size_t)row * QDIM + col];
    if (col < QDIM + KVDIM) return &g_k[(size_t)row * KVDIM + (col - QDIM)];
    return &g_v[(size_t)row * KVDIM + (col - QDIM - KVDIM)];
}

// ---------------------------------------------------------------------------
// GEMM 1: [q|k|v] = X (4096x1024) @ [Wq;Wk;Wv]^T (1536x1024), tf32 mma
// 128x128 block, k-chunk 32, 8 warps (2x4), warp tile 64x32
// Smem stride 36 floats -> conflict-free fragment loads.
// ---------------------------------------------------------------------------
#define GPAD 36

__global__ void __launch_bounds__(256) gemm_qkv(
    const float* __restrict__ X,
    const float* __restrict__ Wq,
    const float* __restrict__ Wk,
    const float* __restrict__ Wv)
{
    __shared__ unsigned As[128 * GPAD];
    __shared__ unsigned Bs[128 * GPAD];

    const int bm = blockIdx.y * 128;
    const int bn = blockIdx.x * 128;
    const int tid = threadIdx.x;
    const int lane = tid & 31;
    const int wid = tid >> 5;
    const int wm = (wid >> 2) * 64;   // 0 or 64
    const int wn = (wid & 3) * 32;    // 0..96
    const int gy = lane >> 2;         // 0..7
    const int gx = lane & 3;          // 0..3

    // staging: each thread loads 4 float4 from A and 4 from B per chunk
    const int srow = tid >> 3;          // base row 0..31 (stride 32 via p)
    const int sc4  = (tid & 7) * 4;     // col 0,4,..,28

    const float* aptr = X + (size_t)(bm + srow) * EE + sc4;
    // B row routing (per staged row; constant across k)
    const float* bptr[4];
    #pragma unroll
    for (int p = 0; p < 4; p++) {
        const int n = bn + srow + 32 * p;
        if (n < QDIM)                bptr[p] = Wq + (size_t)n * EE + sc4;
        else if (n < QDIM + KVDIM)   bptr[p] = Wk + (size_t)(n - QDIM) * EE + sc4;
        else                         bptr[p] = Wv + (size_t)(n - QDIM - KVDIM) * EE + sc4;
    }

    float acc[4][4][4];
    #pragma unroll
    for (int mt = 0; mt < 4; mt++)
        #pragma unroll
        for (int nt = 0; nt < 4; nt++)
            #pragma unroll
            for (int e = 0; e < 4; e++) acc[mt][nt][e] = 0.f;

    float4 ra[4], rb[4];
    #pragma unroll
    for (int p = 0; p < 4; p++) {
        ra[p] = *(const float4*)(aptr + (size_t)(32 * p) * EE);
        rb[p] = *(const float4*)(bptr[p]);
    }

    for (int k0 = 0; k0 < EE; k0 += 32) {
        __syncthreads();
        #pragma unroll
        for (int p = 0; p < 4; p++) {
            const int r = srow + 32 * p;
            unsigned* a = &As[r * GPAD + sc4];
            a[0] = f2tf(ra[p].x); a[1] = f2tf(ra[p].y);
            a[2] = f2tf(ra[p].z); a[3] = f2tf(ra[p].w);
            unsigned* b = &Bs[r * GPAD + sc4];
            b[0] = f2tf(rb[p].x); b[1] = f2tf(rb[p].y);
            b[2] = f2tf(rb[p].z); b[3] = f2tf(rb[p].w);
        }
        __syncthreads();
        if (k0 + 32 < EE) {
            #pragma unroll
            for (int p = 0; p < 4; p++) {
                ra[p] = *(const float4*)(aptr + (size_t)(32 * p) * EE + k0 + 32);
                rb[p] = *(const float4*)(bptr[p] + k0 + 32);
            }
        }
        #pragma unroll
        for (int ks = 0; ks < 4; ks++) {
            unsigned af[4][4], bf[4][2];
            #pragma unroll
            for (int mt = 0; mt < 4; mt++) {
                const int base = (wm + mt * 16 + gy) * GPAD + ks * 8 + gx;
                af[mt][0] = As[base];
                af[mt][1] = As[base + 8 * GPAD];
                af[mt][2] = As[base + 4];
                af[mt][3] = As[base + 8 * GPAD + 4];
            }
            #pragma unroll
            for (int nt = 0; nt < 4; nt++) {
                const int base = (wn + nt * 8 + gy) * GPAD + ks * 8 + gx;
                bf[nt][0] = Bs[base];
                bf[nt][1] = Bs[base + 4];
            }
            #pragma unroll
            for (int mt = 0; mt < 4; mt++)
                #pragma unroll
                for (int nt = 0; nt < 4; nt++)
                    mma8(acc[mt][nt], af[mt][0], af[mt][1], af[mt][2], af[mt][3],
                         bf[nt][0], bf[nt][1]);
        }
    }

    #pragma unroll
    for (int mt = 0; mt < 4; mt++) {
        #pragma unroll
        for (int nt = 0; nt < 4; nt++) {
            const int row = bm + wm + mt * 16 + gy;
            const int col = bn + wn + nt * 8 + 2 * gx;
            float2 v01 = make_float2(acc[mt][nt][0], acc[mt][nt][1]);
            float2 v23 = make_float2(acc[mt][nt][2], acc[mt][nt][3]);
            *(float2*)qkv_ptr(row, col)     = v01;
            *(float2*)qkv_ptr(row + 8, col) = v23;
        }
    }
}

// ---------------------------------------------------------------------------
// GEMM 2: out = y (4096x1024) @ Wproj^T (1024x1024), tf32 mma
// ---------------------------------------------------------------------------
__global__ void __launch_bounds__(256) gemm_proj(
    const float* __restrict__ W, float* __restrict__ C)
{
    __shared__ unsigned As[128 * GPAD];
    __shared__ unsigned Bs[128 * GPAD];

    const int bm = blockIdx.y * 128;
    const int bn = blockIdx.x * 128;
    const int tid = threadIdx.x;
    const int lane = tid & 31;
    const int wid = tid >> 5;
    const int wm = (wid >> 2) * 64;
    const int wn = (wid & 3) * 32;
    const int gy = lane >> 2;
    const int gx = lane & 3;

    const int srow = tid >> 3;
    const int sc4  = (tid & 7) * 4;

    const float* aptr = g_y + (size_t)(bm + srow) * EE + sc4;
    const float* bptr = W + (size_t)(bn + srow) * EE + sc4;

    float acc[4][4][4];
    #pragma unroll
    for (int mt = 0; mt < 4; mt++)
        #pragma unroll
        for (int nt = 0; nt < 4; nt++)
            #pragma unroll
            for (int e = 0; e < 4; e++) acc[mt][nt][e] = 0.f;

    float4 ra[4], rb[4];
    #pragma unroll
    for (int p = 0; p < 4; p++) {
        ra[p] = *(const float4*)(aptr + (size_t)(32 * p) * EE);
        rb[p] = *(const float4*)(bptr + (size_t)(32 * p) * EE);
    }

    for (int k0 = 0; k0 < EE; k0 += 32) {
        __syncthreads();
        #pragma unroll
        for (int p = 0; p < 4; p++) {
            const int r = srow + 32 * p;
            unsigned* a = &As[r * GPAD + sc4];
            a[0] = f2tf(ra[p].x); a[1] = f2tf(ra[p].y);
            a[2] = f2tf(ra[p].z); a[3] = f2tf(ra[p].w);
            unsigned* b = &Bs[r * GPAD + sc4];
            b[0] = f2tf(rb[p].x); b[1] = f2tf(rb[p].y);
            b[2] = f2tf(rb[p].z); b[3] = f2tf(rb[p].w);
        }
        __syncthreads();
        if (k0 + 32 < EE) {
            #pragma unroll
            for (int p = 0; p < 4; p++) {
                ra[p] = *(const float4*)(aptr + (size_t)(32 * p) * EE + k0 + 32);
                rb[p] = *(const float4*)(bptr + (size_t)(32 * p) * EE + k0 + 32);
            }
        }
        #pragma unroll
        for (int ks = 0; ks < 4; ks++) {
            unsigned af[4][4], bf[4][2];
            #pragma unroll
            for (int mt = 0; mt < 4; mt++) {
                const int base = (wm + mt * 16 + gy) * GPAD + ks * 8 + gx;
                af[mt][0] = As[base];
                af[mt][1] = As[base + 8 * GPAD];
                af[mt][2] = As[base + 4];
                af[mt][3] = As[base + 8 * GPAD + 4];
            }
            #pragma unroll
            for (int nt = 0; nt < 4; nt++) {
                const int base = (wn + nt * 8 + gy) * GPAD + ks * 8 + gx;
                bf[nt][0] = Bs[base];
                bf[nt][1] = Bs[base + 4];
            }
            #pragma unroll
            for (int mt = 0; mt < 4; mt++)
                #pragma unroll
                for (int nt = 0; nt < 4; nt++)
                    mma8(acc[mt][nt], af[mt][0], af[mt][1], af[mt][2], af[mt][3],
                         bf[nt][0], bf[nt][1]);
        }
    }

    #pragma unroll
    for (int mt = 0; mt < 4; mt++) {
        #pragma unroll
        for (int nt = 0; nt < 4; nt++) {
            const int row = bm + wm + mt * 16 + gy;
            const int col = bn + wn + nt * 8 + 2 * gx;
            *(float2*)&C[(size_t)row * EE + col] =
                make_float2(acc[mt][nt][0], acc[mt][nt][1]);
            *(float2*)&C[(size_t)(row + 8) * EE + col] =
                make_float2(acc[mt][nt][2], acc[mt][nt][3]);
        }
    }
}

// ---------------------------------------------------------------------------
// Epilogue: RoPE + RMS-norm on q (16 heads) and k (4 heads); gated ve add
// on v (4 heads). One warp per (token, unit), unit in [0,24). (unchanged)
// ---------------------------------------------------------------------------
__global__ void __launch_bounds__(128) rope_gate(
    const float* __restrict__ X, const float* __restrict__ VE,
    const float* __restrict__ Cos, const float* __restrict__ Sin,
    const float* __restrict__ Wgate)
{
    const int gw = blockIdx.x * 4 + (threadIdx.x >> 5);
    const int lane = threadIdx.x & 31;
    const int token = gw / 24;
    const int unit = gw - token * 24;
    const int s = token & (SS - 1);

    if (unit >= 20) {  // v gate
        const int kv = unit - 20;
        const float* xr = X + (size_t)token * EE;
        float g = 0.f;
        #pragma unroll
        for (int c = 0; c < GCH; c++) g = fmaf(xr[c], Wgate[kv * GCH + c], g);
        g = 3.f / (1.f + __expf(-g));
        float* vb = g_v + (size_t)token * KVDIM + kv * HDD;
        const float* veb = VE + (size_t)token * KVDIM + kv * HDD;
        vb[lane]      += g * veb[lane];
        vb[lane + 32] += g * veb[lane + 32];
        return;
    }

    float* base = (unit < NHH)
        ? g_q + (size_t)token * QDIM + unit * HDD
        : g_k + (size_t)token * KVDIM + (unit - NHH) * HDD;

    const float c  = Cos[s * 32 + lane];
    const float sn = Sin[s * 32 + lane];
    const float x1 = base[lane];
    const float x2 = base[lane + 32];
    const float o1 =  x1 * c + x2 * sn;
    const float o2 = -x1 * sn + x2 * c;
    float ssum = o1 * o1 + o2 * o2;
    #pragma unroll
    for (int off = 16; off; off >>= 1)
        ssum += __shfl_xor_sync(0xffffffffu, ssum, off);
    const float inv = rsqrtf(ssum * (1.f / 64.f) + 1.1920928955078125e-07f) * 1.2f;
    base[lane]      = o1 * inv;
    base[lane + 32] = o2 * inv;
}

// ---------------------------------------------------------------------------
// Flash attention on tensor cores: causal, GQA, 64x64 tiles, tf32 mma.
// 4 warps, each owns a 16-row band. Q frags hoisted to regs; Q smem buffer
// reused for P (bands are warp-private). Smem row stride 72 -> conflict-free
// fragment loads (banks 8g+t). Dynamic smem 3*64*72*4 = 55296 B.
// ---------------------------------------------------------------------------
#define APAD 72
#define ATTN_SMEM_BYTES (3 * 64 * APAD * 4)

__global__ void __launch_bounds__(128) attn_kernel()
{
    extern __shared__ unsigned sm[];
    unsigned* Qs = sm;                 // reused as P after frag extraction
    unsigned* Ks = sm + 64 * APAD;
    unsigned* Vs = sm + 2 * 64 * APAD;

    const int qt = blockIdx.x;         // q tile (32)
    const int h  = blockIdx.y;         // head (16)
    const int b  = blockIdx.z;         // batch (2)
    const int hkv = h >> 2;
    const int q0 = qt * 64;
    const int tid = threadIdx.x;
    const int lane = tid & 31;
    const int wid = tid >> 5;          // 0..3
    const int gy = lane >> 2;          // 0..7
    const int gx = lane & 3;           // 0..3
    const int r0 = wid * 16 + gy;      // local q row (second row = r0+8)

    // Stage Q (scaled by 1/sqrt(HD)=0.125), convert to tf32
    for (int idx = tid; idx < 64 * 16; idx += 128) {
        const int r = idx >> 4, c4 = (idx & 15) * 4;
        float4 v = *(const float4*)&g_q[(size_t)(b * SS + q0 + r) * QDIM + h * HDD + c4];
        unsigned* q = &Qs[r * APAD + c4];
        q[0] = f2tf(v.x * 0.125f); q[1] = f2tf(v.y * 0.125f);
        q[2] = f2tf(v.z * 0.125f); q[3] = f2tf(v.w * 0.125f);
    }
    __syncthreads();

    // Extract Q fragments (reused across all k-tiles)
    unsigned qa[8][4];
    #pragma unroll
    for (int ks = 0; ks < 8; ks++) {
        const int base = r0 * APAD + ks * 8 + gx;
        qa[ks][0] = Qs[base];
        qa[ks][1] = Qs[base + 8 * APAD];
        qa[ks][2] = Qs[base + 4];
        qa[ks][3] = Qs[base + 8 * APAD + 4];
    }

    float Oa[8][4];
    #pragma unroll
    for (int nt = 0; nt < 8; nt++)
        #pragma unroll
        for (int e = 0; e < 4; e++) Oa[nt][e] = 0.f;
    float m0 = -1e30f, m1 = -1e30f, l0 = 0.f, l1 = 0.f;

    for (int j = 0; j <= qt; j++) {
        __syncthreads();   // prior-iter K/V/P consumers done; Q extraction done (j=0)
        const int kbase = b * SS + j * 64;
        for (int idx = tid; idx < 64 * 16; idx += 128) {
            const int r = idx >> 4, c4 = (idx & 15) * 4;
            float4 kv = *(const float4*)&g_k[(size_t)(kbase + r) * KVDIM + hkv * HDD + c4];
            float4 vv = *(const float4*)&g_v[(size_t)(kbase + r) * KVDIM + hkv * HDD + c4];
            unsigned* kd = &Ks[r * APAD + c4];
            kd[0] = f2tf(kv.x); kd[1] = f2tf(kv.y); kd[2] = f2tf(kv.z); kd[3] = f2tf(kv.w);
            unsigned* vd = &Vs[r * APAD + c4];
            vd[0] = f2tf(vv.x); vd[1] = f2tf(vv.y); vd[2] = f2tf(vv.z); vd[3] = f2tf(vv.w);
        }
        __syncthreads();

        // S = Q K^T  (B[kd][tok] = K[tok][kd])
        float sf[8][4];
        #pragma unroll
        for (int nt = 0; nt < 8; nt++)
            #pragma unroll
            for (int e = 0; e < 4; e++) sf[nt][e] = 0.f;
        #pragma unroll
        for (int ks = 0; ks < 8; ks++) {
            #pragma unroll
            for (int nt = 0; nt < 8; nt++) {
                const int base = (nt * 8 + gy) * APAD + ks * 8 + gx;
                mma8(sf[nt], qa[ks][0], qa[ks][1], qa[ks][2], qa[ks][3],
                     Ks[base], Ks[base + 4]);
            }
        }

        // causal mask (diagonal tile only); scale folded into Q
        if (j == qt) {
            #pragma unroll
            for (int nt = 0; nt < 8; nt++) {
                const int c = nt * 8 + 2 * gx;
                if (c     > r0)     sf[nt][0] = -1e30f;
                if (c + 1 > r0)     sf[nt][1] = -1e30f;
                if (c     > r0 + 8) sf[nt][2] = -1e30f;
                if (c + 1 > r0 + 8) sf[nt][3] = -1e30f;
            }
        }

        // online softmax for rows r0 (elems 0,1) and r0+8 (elems 2,3)
        float mx0 = -1e30f, mx1 = -1e30f;
        #pragma unroll
        for (int nt = 0; nt < 8; nt++) {
            mx0 = fmaxf(mx0, fmaxf(sf[nt][0], sf[nt][1]));
            mx1 = fmaxf(mx1, fmaxf(sf[nt][2], sf[nt][3]));
        }
        mx0 = fmaxf(mx0, __shfl_xor_sync(0xffffffffu, mx0, 1));
        mx0 = fmaxf(mx0, __shfl_xor_sync(0xffffffffu, mx0, 2));
        mx1 = fmaxf(mx1, __shfl_xor_sync(0xffffffffu, mx1, 1));
        mx1 = fmaxf(mx1, __shfl_xor_sync(0xffffffffu, mx1, 2));
        const float mn0 = fmaxf(m0, mx0);
        const float mn1 = fmaxf(m1, mx1);
        float ps0 = 0.f, ps1 = 0.f;
        #pragma unroll
        for (int nt = 0; nt < 8; nt++) {
            sf[nt][0] = __expf(sf[nt][0] - mn0);
            sf[nt][1] = __expf(sf[nt][1] - mn0);
            sf[nt][2] = __expf(sf[nt][2] - mn1);
            sf[nt][3] = __expf(sf[nt][3] - mn1);
            ps0 += sf[nt][0] + sf[nt][1];
            ps1 += sf[nt][2] + sf[nt][3];
        }
        ps0 += __shfl_xor_sync(0xffffffffu, ps0, 1);
        ps0 += __shfl_xor_sync(0xffffffffu, ps0, 2);
        ps1 += __shfl_xor_sync(0xffffffffu, ps1, 1);
        ps1 += __shfl_xor_sync(0xffffffffu, ps1, 2);
        const float scl0 = __expf(m0 - mn0);
        const float scl1 = __expf(m1 - mn1);
        l0 = l0 * scl0 + ps0;
        l1 = l1 * scl1 + ps1;
        m0 = mn0; m1 = mn1;

        // store P into Q buffer (warp-private 16-row band)
        #pragma unroll
        for (int nt = 0; nt < 8; nt++) {
            const int a = r0 * APAD + nt * 8 + 2 * gx;
            Qs[a]     = f2tf(sf[nt][0]);
            Qs[a + 1] = f2tf(sf[nt][1]);
            Qs[a + 8 * APAD]     = f2tf(sf[nt][2]);
            Qs[a + 8 * APAD + 1] = f2tf(sf[nt][3]);
        }
        __syncwarp();

        // rescale O
        #pragma unroll
        for (int nt = 0; nt < 8; nt++) {
            Oa[nt][0] *= scl0; Oa[nt][1] *= scl0;
            Oa[nt][2] *= scl1; Oa[nt][3] *= scl1;
        }

        // O += P V   (A = P band from smem, B = V[tok][hd])
        #pragma unroll
        for (int ks = 0; ks < 8; ks++) {
            const int pb = r0 * APAD + ks * 8 + gx;
            const unsigned pa0 = Qs[pb];
            const unsigned pa1 = Qs[pb + 8 * APAD];
            const unsigned pa2 = Qs[pb + 4];
            const unsigned pa3 = Qs[pb + 8 * APAD + 4];
            #pragma unroll
            for (int nt = 0; nt < 8; nt++) {
                const int vb = (ks * 8 + gx) * APAD + nt * 8 + gy;
                mma8(Oa[nt], pa0, pa1, pa2, pa3, Vs[vb], Vs[vb + 4 * APAD]);
            }
        }
    }

    // epilogue: normalize and store
    const float inv0 = 1.f / l0;
    const float inv1 = 1.f / l1;
    const size_t row0 = (size_t)(b * SS + q0 + r0) * QDIM + h * HDD;
    const size_t row1 = (size_t)(b * SS + q0 + r0 + 8) * QDIM + h * HDD;
    #pragma unroll
    for (int nt = 0; nt < 8; nt++) {
        const int col = nt * 8 + 2 * gx;
        *(float2*)&g_y[row0 + col] = make_float2(Oa[nt][0] * inv0, Oa[nt][1] * inv0);
        *(float2*)&g_y[row1 + col] = make_float2(Oa[nt][2] * inv1, Oa[nt][3] * inv1);
    }
}

// ---------------------------------------------------------------------------
// Launch: qkv GEMM -> rope/rms/gate -> flash attention -> proj GEMM
// Inputs: 0 x, 1 ve, 2 cos, 3 sin, 4 attn_mask(unused), 5 Wq, 6 Wk, 7 Wv,
//         8 Wproj, 9 Wgate. Output: float32 (B,S,E).
// ---------------------------------------------------------------------------
extern "C" void kernel_launch(void* const* d_in, const int* in_sizes, int n_in,
                              void* d_out, int out_size)
{
    const float* x     = (const float*)d_in[0];
    const float* ve    = (const float*)d_in[1];
    const float* cosb  = (const float*)d_in[2];
    const float* sinb  = (const float*)d_in[3];
    const float* Wq    = (const float*)d_in[5];
    const float* Wk    = (const float*)d_in[6];
    const float* Wv    = (const float*)d_in[7];
    const float* Wproj = (const float*)d_in[8];
    const float* Wgate = (const float*)d_in[9];
    float* out = (float*)d_out;

    (void)in_sizes; (void)n_in; (void)out_size;

    cudaFuncSetAttribute(attn_kernel,
                         cudaFuncAttributeMaxDynamicSharedMemorySize,
                         ATTN_SMEM_BYTES);

    // 1) QKV projection: grid (1536/128, 4096/128)
    gemm_qkv<<<dim3(12, 32), 256>>>(x, Wq, Wk, Wv);

    // 2) RoPE + RMS + gated-ve
    rope_gate<<<(MM * 24) / 4, 128>>>(x, ve, cosb, sinb, Wgate);

    // 3) Flash attention (tensor cores): (q-tiles, heads, batch)
    attn_kernel<<<dim3(SS / 64, NHH, BB), 128, ATTN_SMEM_BYTES>>>();

    // 4) Output projection: grid (1024/128, 4096/128)
    gemm_proj<<<dim3(8, 32), 256>>>(Wproj, out);
}